// round 5
// baseline (speedup 1.0000x reference)
#include <cuda_runtime.h>
#include <stdint.h>

// B = 1048576, D = 3, L = 16, C = 2, H = 16, S = 1.0
//   res(l) = 16 << l, side = res+1; dense l=0,1,2; hashed l>=3 (hm = 2^19)
//   offsets: 0, 4920, 40864, 315496, then +524288/level (all even)
//   table = concat(ext[524288,2], own[.,2])
//
// R5: level-uniform warps. Block = 16 warps x 32 lanes; warp w == level w,
// lane == point within a 32-point tile. Level-0 table (4920 float2, 39.4KB)
// lives in smem: warp 0 gathers via LDS (warp-uniform branch, no R4-style
// serialization). Warps 1-15 run the R2 pair-merged global-gather path with
// uniform level constants. Outputs transposed through smem for coalesced
// 256B/warp stores. Persistent grid (592x512) amortizes the table preload.

#define HASH_SPLIT 524288u
#define P2 2654435761u
#define P3 805459861u

#define NTHREADS 512
#define NBLOCKS  592           // 148 SMs x 4 blocks
#define B_PTS    1048576u
#define TILE     32u
#define STRIDE   (NBLOCKS * TILE)   // 18944 points per grid wave
#define L0_SIZE  4920

__device__ __forceinline__ const float2* tptr(unsigned g,
                                              const float2* __restrict__ ext,
                                              const float2* __restrict__ own)
{
    return (g < HASH_SPLIT) ? (ext + g) : (own + (g - HASH_SPLIT));
}

__global__ void __launch_bounds__(NTHREADS, 4)
grid_encode_kernel(const float* __restrict__ pts,
                   const float2* __restrict__ ext,
                   const float2* __restrict__ own,
                   float2* __restrict__ out)
{
    __shared__ float  s_pts[TILE * 3];        // 384 B
    __shared__ float2 s_out[TILE][17];        // 4352 B (17 pad: 2-way max)
    __shared__ float2 s_tab[L0_SIZE];         // 39360 B  -> total 44.1 KB

    // Preload level-0 table once per block (coalesced).
    for (int i = threadIdx.x; i < L0_SIZE; i += NTHREADS)
        s_tab[i] = ext[i];

    const unsigned w    = threadIdx.x >> 5;   // level (warp-uniform)
    const unsigned lane = threadIdx.x & 31u;  // point within tile

    // Warp-uniform level constants.
    const unsigned res   = 16u << w;
    const float    scale = (float)(res - 1u);
    const unsigned side  = res + 1u;
    const unsigned side2 = side * side;
    const bool     hashed = (w >= 3u);
    const unsigned off = hashed ? (315496u + (w - 3u) * 524288u)
                                : (w == 0u ? 0u : (w == 1u ? 4920u : 40864u));

    for (unsigned base = blockIdx.x * TILE; base < B_PTS; base += STRIDE) {
        // Stage this tile's coords (96 contiguous floats).
        if (threadIdx.x < TILE * 3u)
            s_pts[threadIdx.x] = pts[base * 3u + threadIdx.x];
        __syncthreads();

        // lane*3 mod 32 is a bijection (gcd(3,32)=1): conflict-free reads.
        const float px = s_pts[lane * 3u + 0u];
        const float py = s_pts[lane * 3u + 1u];
        const float pz = s_pts[lane * 3u + 2u];

        const float posx = (px + 1.0f) * 0.5f * scale + 0.5f;
        const float posy = (py + 1.0f) * 0.5f * scale + 0.5f;
        const float posz = (pz + 1.0f) * 0.5f * scale + 0.5f;

        const float flx = floorf(posx);
        const float fly = floorf(posy);
        const float flz = floorf(posz);
        const float fx = posx - flx;
        const float fy = posy - fly;
        const float fz = posz - flz;
        const unsigned x0 = (unsigned)flx;
        const unsigned y0 = (unsigned)fly;
        const unsigned z0 = (unsigned)flz;

        const float wx0 = 1.0f - fx, wx1 = fx;
        const float wyv[2] = { 1.0f - fy, fy };
        const float wzv[2] = { 1.0f - fz, fz };

        float accx = 0.0f, accy = 0.0f;

        if (w == 0u) {
            // Level 0: dense side=17, off=0, whole table in smem (idx<=4912).
            const unsigned base0 = x0 + y0 * 17u + z0 * 289u;
#pragma unroll
            for (int q = 0; q < 4; ++q) {
                const int cy = q & 1, cz = (q >> 1) & 1;
                const unsigned ix = base0 + (unsigned)cy * 17u
                                          + (unsigned)cz * 289u;
                const float2 va = s_tab[ix];
                const float2 vb = s_tab[ix + 1u];
                const float wyz = wyv[cy] * wzv[cz];
                accx += wyz * (wx0 * va.x + wx1 * vb.x);
                accy += wyz * (wx0 * va.y + wx1 * vb.y);
            }
        } else {
            // Hash per-axis terms (uint32 wraparound; PRIMES = {1, P2, P3}).
            const unsigned hy0 = y0 * P2;
            const unsigned hz0 = z0 * P3;
            const unsigned hys[2] = { hy0, hy0 + P2 };
            const unsigned hzs[2] = { hz0, hz0 + P3 };
            // Dense per-axis terms (no modulo: side^3 <= hm for l<=2).
            const unsigned dys[2] = { y0 * side,  y0 * side + side };
            const unsigned dzs[2] = { z0 * side2, z0 * side2 + side2 };

            unsigned ia[4], ib[4];
#pragma unroll
            for (int q = 0; q < 4; ++q) {
                const int cy = q & 1, cz = (q >> 1) & 1;
                unsigned a, bx;
                if (hashed) {
                    const unsigned hb = hys[cy] ^ hzs[cz];
                    a  = (x0 ^ hb) & (HASH_SPLIT - 1u);
                    bx = ((x0 + 1u) ^ hb) & (HASH_SPLIT - 1u);
                } else {
                    const unsigned db = dys[cy] + dzs[cz];
                    a  = x0 + db;
                    bx = a + 1u;
                }
                ia[q] = off + a;
                ib[q] = off + bx;
            }

            // R2 fetch: one aligned LDG.128 when the x-pair shares a 16B
            // slot ((a^b)==1), else two LDG.64. Pairs never cross level or
            // ext/own boundaries (all even).
            float2 v0[4], v1[4];
#pragma unroll
            for (int q = 0; q < 4; ++q) {
                const unsigned a = ia[q], bb = ib[q];
                if ((a ^ bb) == 1u) {
                    const unsigned lo = a & ~1u;
                    const float4 w4 = __ldg((const float4*)tptr(lo, ext, own));
                    const bool swap = (a & 1u);
                    v0[q] = swap ? make_float2(w4.z, w4.w)
                                 : make_float2(w4.x, w4.y);
                    v1[q] = swap ? make_float2(w4.x, w4.y)
                                 : make_float2(w4.z, w4.w);
                } else {
                    v0[q] = __ldg(tptr(a,  ext, own));
                    v1[q] = __ldg(tptr(bb, ext, own));
                }
            }

#pragma unroll
            for (int q = 0; q < 4; ++q) {
                const int cy = q & 1, cz = (q >> 1) & 1;
                const float wyz = wyv[cy] * wzv[cz];
                accx += wyz * (wx0 * v0[q].x + wx1 * v1[q].x);
                accy += wyz * (wx0 * v0[q].y + wx1 * v1[q].y);
            }
        }

        // Transpose through smem for coalesced stores.
        s_out[lane][w] = make_float2(accx, accy);
        __syncthreads();

        const unsigned sp = threadIdx.x >> 4;     // point 0..31
        const unsigned sl = threadIdx.x & 15u;    // level 0..15
        out[(base + sp) * 16u + sl] = s_out[sp][sl];
        __syncthreads();   // protect s_pts/s_out before next iteration
    }
}

extern "C" void kernel_launch(void* const* d_in, const int* in_sizes, int n_in,
                              void* d_out, int out_size)
{
    const float*  pts = (const float*)d_in[0];        // [B, 3]
    const float2* ext = (const float2*)d_in[1];       // [524288, 2]
    const float2* own = (const float2*)d_in[2];       // [N_TABLE - 524288, 2]
    float2* out = (float2*)d_out;                     // [B*16] float2

    grid_encode_kernel<<<NBLOCKS, NTHREADS>>>(pts, ext, own, out);
}

// round 6
// speedup vs baseline: 1.3792x; 1.3792x over previous
#include <cuda_runtime.h>
#include <stdint.h>

// B = 1048576, D = 3, L = 16, C = 2, H = 16, S = 1.0
//   res(l) = 16 << l, side = res+1; dense l=0,1,2; hashed l>=3 (hm = 2^19)
//   offsets: 0, 4920, 40864, 315496, then +524288/level (all even)
//   table = concat(ext[524288,2], own[.,2])
//
// R6 = R2 skeleton (best so far: gtid = b*16+l, pair-merged gathers, no
// barriers, no persistence) + cache-flavor split:
//   - hashed levels (l>=3, 81% of gathers, ~0% L1 hit over 53MB) use __ldcg:
//     L2-only, no L1 allocation -> stop thrashing L1.
//   - dense levels (l<=2; tables 39KB/287KB/2.2MB) use __ldg and now stay
//     L1-resident, converting their L2 sectors into L1 hits.

#define HASH_SPLIT 524288u
#define P2 2654435761u
#define P3 805459861u

__device__ __forceinline__ const float2* tptr(unsigned g,
                                              const float2* __restrict__ ext,
                                              const float2* __restrict__ own)
{
    return (g < HASH_SPLIT) ? (ext + g) : (own + (g - HASH_SPLIT));
}

// Pair-merged gather + trilinear accumulate. CG=true -> L2-only loads.
template<bool CG>
__device__ __forceinline__ float2 gather_accum(
    const unsigned* __restrict__ ia, const unsigned* __restrict__ ib,
    const float2* __restrict__ ext, const float2* __restrict__ own,
    float wx0, float wx1, const float* wyv, const float* wzv)
{
    float2 v0[4], v1[4];
#pragma unroll
    for (int q = 0; q < 4; ++q) {
        const unsigned a = ia[q], bb = ib[q];
        if ((a ^ bb) == 1u) {
            // Pair shares one aligned 16B slot: single LDG.128.
            const unsigned lo = a & ~1u;
            const float4* p4 = (const float4*)tptr(lo, ext, own);
            const float4 w4 = CG ? __ldcg(p4) : __ldg(p4);
            const bool swap = (a & 1u);
            v0[q] = swap ? make_float2(w4.z, w4.w) : make_float2(w4.x, w4.y);
            v1[q] = swap ? make_float2(w4.x, w4.y) : make_float2(w4.z, w4.w);
        } else {
            const float2* pa = tptr(a,  ext, own);
            const float2* pb = tptr(bb, ext, own);
            v0[q] = CG ? __ldcg(pa) : __ldg(pa);
            v1[q] = CG ? __ldcg(pb) : __ldg(pb);
        }
    }

    float accx = 0.0f, accy = 0.0f;
#pragma unroll
    for (int q = 0; q < 4; ++q) {
        const int cy = q & 1, cz = (q >> 1) & 1;
        const float wyz = wyv[cy] * wzv[cz];
        accx += wyz * (wx0 * v0[q].x + wx1 * v1[q].x);
        accy += wyz * (wx0 * v0[q].y + wx1 * v1[q].y);
    }
    return make_float2(accx, accy);
}

__global__ void __launch_bounds__(256)
grid_encode_kernel(const float* __restrict__ pts,
                   const float2* __restrict__ ext,
                   const float2* __restrict__ own,
                   float2* __restrict__ out)
{
    const unsigned gtid = blockIdx.x * 256u + threadIdx.x;
    const unsigned b = gtid >> 4;
    const unsigned l = gtid & 15u;

    const float px_in = __ldg(&pts[3u * b + 0u]);
    const float py_in = __ldg(&pts[3u * b + 1u]);
    const float pz_in = __ldg(&pts[3u * b + 2u]);

    const unsigned res  = 16u << l;
    const float scale   = (float)(res - 1u);
    const unsigned side = res + 1u;

    const float posx = (px_in + 1.0f) * 0.5f * scale + 0.5f;
    const float posy = (py_in + 1.0f) * 0.5f * scale + 0.5f;
    const float posz = (pz_in + 1.0f) * 0.5f * scale + 0.5f;

    const float flx = floorf(posx);
    const float fly = floorf(posy);
    const float flz = floorf(posz);
    const float fx = posx - flx;
    const float fy = posy - fly;
    const float fz = posz - flz;
    const unsigned x0 = (unsigned)flx;
    const unsigned y0 = (unsigned)fly;
    const unsigned z0 = (unsigned)flz;

    const bool hashed = (l >= 3u);
    const unsigned off = hashed ? (315496u + (l - 3u) * 524288u)
                                : (l == 0u ? 0u : (l == 1u ? 4920u : 40864u));

    // Hash per-axis terms (uint32 wraparound; PRIMES = {1, P2, P3})
    const unsigned hy0 = y0 * P2;
    const unsigned hz0 = z0 * P3;
    const unsigned hys[2] = { hy0, hy0 + P2 };
    const unsigned hzs[2] = { hz0, hz0 + P3 };

    // Dense per-axis terms (no modulo: side^3 <= hm for l<=2)
    const unsigned side2 = side * side;
    const unsigned dys[2] = { y0 * side,  y0 * side + side };
    const unsigned dzs[2] = { z0 * side2, z0 * side2 + side2 };

    unsigned ia[4], ib[4];
#pragma unroll
    for (int p = 0; p < 4; ++p) {
        const int cy = p & 1, cz = (p >> 1) & 1;
        unsigned a, bx;
        if (hashed) {
            const unsigned hb = hys[cy] ^ hzs[cz];
            a  = (x0 ^ hb) & (HASH_SPLIT - 1u);
            bx = ((x0 + 1u) ^ hb) & (HASH_SPLIT - 1u);
        } else {
            const unsigned db = dys[cy] + dzs[cz];
            a  = x0 + db;
            bx = a + 1u;
        }
        ia[p] = off + a;
        ib[p] = off + bx;
    }

    const float wx0 = 1.0f - fx, wx1 = fx;
    const float wyv[2] = { 1.0f - fy, fy };
    const float wzv[2] = { 1.0f - fz, fz };

    float2 acc;
    if (hashed) {
        // L2-only loads: don't allocate L1 for the 53MB hashed region.
        acc = gather_accum<true>(ia, ib, ext, own, wx0, wx1, wyv, wzv);
    } else {
        // Dense tables stay L1-resident.
        acc = gather_accum<false>(ia, ib, ext, own, wx0, wx1, wyv, wzv);
    }

    out[gtid] = acc;
}

extern "C" void kernel_launch(void* const* d_in, const int* in_sizes, int n_in,
                              void* d_out, int out_size)
{
    const float*  pts = (const float*)d_in[0];        // [B, 3]
    const float2* ext = (const float2*)d_in[1];       // [524288, 2]
    const float2* own = (const float2*)d_in[2];       // [N_TABLE - 524288, 2]
    float2* out = (float2*)d_out;                     // [B*16] float2

    grid_encode_kernel<<<65536, 256>>>(pts, ext, own, out);
}